// round 2
// baseline (speedup 1.0000x reference)
#include <cuda_runtime.h>
#include <cstdint>

// Problem constants
#define NPTS   8192
#define VVAR   5
#define HDIM   256
#define TM     32          // points per block tile
#define PITCH  36          // smem row pitch (floats): 16B-aligned rows, (4t+m)%32 -> 4-way write conflicts max
#define NTHREADS 256

// smem layout (floats): bufA[256*PITCH] | bufB[256*PITCH] | coord_s[TM*3]
#define BUF_FLOATS   (HDIM * PITCH)
#define COORD_OFF    (2 * BUF_FLOATS)
#define SMEM_FLOATS  (2 * BUF_FLOATS + TM * 3)
#define SMEM_BYTES   (SMEM_FLOATS * 4)

// Precomputed per-(v,feature) constant: pt = ba1 + relu(pe) @ Wa1_param
__device__ float g_pt[VVAR * HDIM];

// ---------- packed f32x2 helpers (Blackwell FFMA2) ----------
__device__ __forceinline__ unsigned long long pack2(float w) {
    unsigned long long r;
    asm("mov.b64 %0, {%1, %1};" : "=l"(r) : "r"(__float_as_uint(w)));
    return r;
}
__device__ __forceinline__ unsigned long long ffma2(unsigned long long a,
                                                    unsigned long long b,
                                                    unsigned long long c) {
    unsigned long long d;
    asm("fma.rn.f32x2 %0, %1, %2, %3;" : "=l"(d) : "l"(a), "l"(b), "l"(c));
    return d;
}
__device__ __forceinline__ float2 unpack2(unsigned long long a) {
    unsigned int lo, hi;
    asm("mov.b64 {%0, %1}, %2;" : "=r"(lo), "=r"(hi) : "l"(a));
    return make_float2(__uint_as_float(lo), __uint_as_float(hi));
}

// Accumulate one 256-deep GEMM column: acc[m] += sum_k buf[k][m] * W[k*256]
// buf is k-major (rows of PITCH floats). W points at &Wmat[0*256 + t].
// Smem reads are warp-uniform (broadcast, conflict-free); weight loads are coalesced.
__device__ __forceinline__ void gemm_acc(const float* __restrict__ buf,
                                         const float* __restrict__ W,
                                         unsigned long long* acc) {
    float wcur[4], wnxt[4];
#pragma unroll
    for (int j = 0; j < 4; j++) wcur[j] = __ldg(W + j * HDIM);
#pragma unroll 1
    for (int k4 = 0; k4 < 64; k4++) {
        const float* Wn = W + (((k4 + 1) & 63) * 4) * HDIM;  // wraps on last iter (harmless)
#pragma unroll
        for (int j = 0; j < 4; j++) wnxt[j] = __ldg(Wn + j * HDIM);
#pragma unroll
        for (int j = 0; j < 4; j++) {
            unsigned long long ww = pack2(wcur[j]);
            const float* row = buf + (k4 * 4 + j) * PITCH;
#pragma unroll
            for (int i = 0; i < TM / 4; i++) {
                ulonglong2 a = *reinterpret_cast<const ulonglong2*>(row + 4 * i);
                acc[2 * i]     = ffma2(a.x, ww, acc[2 * i]);
                acc[2 * i + 1] = ffma2(a.y, ww, acc[2 * i + 1]);
            }
        }
#pragma unroll
        for (int j = 0; j < 4; j++) wcur[j] = wnxt[j];
    }
}

// ---------- pre-kernel: pt[v][t] = ba1[v][t] + sum_d relu(pe)[d] * Wa1_param[v][d][t] ----------
__global__ void precompute_pt_kernel(const float* __restrict__ gpv,
                                     const float* __restrict__ gpr,
                                     const float* __restrict__ Wp,
                                     const float* __restrict__ bp,
                                     const float* __restrict__ Wa1_param,
                                     const float* __restrict__ ba1) {
    __shared__ float pe_s[HDIM];
    const int t = threadIdx.x;
    const int v = blockIdx.x;
    float r0 = __ldg(gpv + 0) / __ldg(gpr + 0);
    float r1 = __ldg(gpv + 1) / __ldg(gpr + 1);
    float pe = fmaf(r0, __ldg(Wp + t), fmaf(r1, __ldg(Wp + HDIM + t), __ldg(bp + t)));
    pe_s[t] = fmaxf(pe, 0.f);
    __syncthreads();
    float pt = __ldg(ba1 + v * HDIM + t);
    const float* Wpar = Wa1_param + v * HDIM * HDIM + t;
#pragma unroll 8
    for (int d = 0; d < HDIM; d++) pt = fmaf(pe_s[d], __ldg(Wpar + d * HDIM), pt);
    g_pt[v * HDIM + t] = pt;
}

// ---------- main fused kernel ----------
__global__ void __launch_bounds__(NTHREADS, 2)
solution_volume_kernel(const float* __restrict__ coords,      // (N,3)
                       const float* __restrict__ enc_g,       // (N,256)
                       const float* __restrict__ enc_node,    // (N,256)
                       const float* __restrict__ Wb1,         // (V,3,256)
                       const float* __restrict__ bb1,         // (V,256)
                       const float* __restrict__ Wb2,         // (V,256,256)
                       const float* __restrict__ bb2,         // (V,256)
                       const float* __restrict__ Wa1_basis,   // (V,256,256)
                       const float* __restrict__ Wa1_node,    // (V,256,256)
                       const float* __restrict__ Wa1_geo,     // (V,256,256)
                       const float* __restrict__ Wa2,         // (V,256)
                       const float* __restrict__ ba2,         // (V,)
                       float* __restrict__ out)               // (N,V)
{
    extern __shared__ float sm[];
    float* bufA    = sm;
    float* bufB    = sm + BUF_FLOATS;
    float* coord_s = sm + COORD_OFF;

    const int t  = threadIdx.x;          // column index h/g (0..255)
    const int v  = blockIdx.y;           // variable
    const int n0 = blockIdx.x * TM;      // first point of tile

    // ---- stage 0: coords tile -> smem; pt from precomputed global ----
    if (t < TM * 3) coord_s[t] = __ldg(coords + n0 * 3 + t);
    const float pt = g_pt[v * HDIM + t];

    // ---- stage 1: h1[t][m] = relu(coords @ Wb1 + bb1) -> bufA rows (k-major) ----
    {
        const float* wb = Wb1 + v * 3 * HDIM + t;
        float w0 = __ldg(wb), w1 = __ldg(wb + HDIM), w2 = __ldg(wb + 2 * HDIM);
        float b1 = __ldg(bb1 + v * HDIM + t);
        __syncthreads();   // coord_s ready
        float* rowA = bufA + t * PITCH;
#pragma unroll
        for (int m = 0; m < TM; m++) {
            float h = fmaf(w0, coord_s[3 * m + 0],
                      fmaf(w1, coord_s[3 * m + 1],
                      fmaf(w2, coord_s[3 * m + 2], b1)));
            rowA[m] = fmaxf(h, 0.f);
        }
    }
    __syncthreads();

    unsigned long long acc[TM / 2];
#pragma unroll
    for (int i = 0; i < TM / 2; i++) acc[i] = 0ull;

    // ---- stage 2: h2 = relu(h1 @ Wb2 + bb2) -> bufB rows ----
    gemm_acc(bufA, Wb2 + v * HDIM * HDIM + t, acc);
    {
        float b2 = __ldg(bb2 + v * HDIM + t);
        float* rowB = bufB + t * PITCH;
#pragma unroll
        for (int i = 0; i < TM / 2; i++) {
            float2 f = unpack2(acc[i]);
            rowB[2 * i]     = fmaxf(f.x + b2, 0.f);
            rowB[2 * i + 1] = fmaxf(f.y + b2, 0.f);
        }
    }
    __syncthreads();   // bufB complete, bufA free

    // ---- stage 3: z accumulation (node + geo + basis) ----
#pragma unroll
    for (int i = 0; i < TM / 2; i++) acc[i] = 0ull;

    // node tile -> bufA (transposed: bufA[d][m] = enc_node[n0+m][d])
    {
        float* rowA = bufA + t * PITCH;
#pragma unroll 4
        for (int m = 0; m < TM; m++) rowA[m] = __ldg(enc_node + (size_t)(n0 + m) * HDIM + t);
    }
    __syncthreads();
    gemm_acc(bufA, Wa1_node + v * HDIM * HDIM + t, acc);
    __syncthreads();   // all reads of bufA done

    // geo tile -> bufA
    {
        float* rowA = bufA + t * PITCH;
#pragma unroll 4
        for (int m = 0; m < TM; m++) rowA[m] = __ldg(enc_g + (size_t)(n0 + m) * HDIM + t);
    }
    __syncthreads();
    gemm_acc(bufA, Wa1_geo + v * HDIM * HDIM + t, acc);
    gemm_acc(bufB, Wa1_basis + v * HDIM * HDIM + t, acc);   // bufB read-only here, no extra sync
    __syncthreads();   // all reads of bufA done before overwrite

    // ---- stage 4: a1 = relu(z + pt); partials p[t][m] = a1*Wa2 -> bufA; reduce over t ----
    {
        float w2v = __ldg(Wa2 + v * HDIM + t);
        float* rowA = bufA + t * PITCH;
#pragma unroll
        for (int i = 0; i < TM / 2; i++) {
            float2 f = unpack2(acc[i]);
            rowA[2 * i]     = fmaxf(f.x + pt, 0.f) * w2v;
            rowA[2 * i + 1] = fmaxf(f.y + pt, 0.f) * w2v;
        }
    }
    __syncthreads();

    if (t < TM) {
        float s = __ldg(ba2 + v);
#pragma unroll 8
        for (int k = 0; k < HDIM; k++) s += bufA[k * PITCH + t];
        out[(size_t)(n0 + t) * VVAR + v] = s;
    }
}

extern "C" void kernel_launch(void* const* d_in, const int* in_sizes, int n_in,
                              void* d_out, int out_size) {
    const float* coords    = (const float*)d_in[0];
    const float* enc_g     = (const float*)d_in[1];
    const float* enc_node  = (const float*)d_in[2];
    const float* gpv       = (const float*)d_in[3];
    const float* gpr       = (const float*)d_in[4];
    const float* Wb1       = (const float*)d_in[5];
    const float* bb1       = (const float*)d_in[6];
    const float* Wb2       = (const float*)d_in[7];
    const float* bb2       = (const float*)d_in[8];
    const float* Wp        = (const float*)d_in[9];
    const float* bp        = (const float*)d_in[10];
    const float* Wa1_basis = (const float*)d_in[11];
    const float* Wa1_node  = (const float*)d_in[12];
    const float* Wa1_geo   = (const float*)d_in[13];
    const float* Wa1_param = (const float*)d_in[14];
    const float* ba1       = (const float*)d_in[15];
    const float* Wa2       = (const float*)d_in[16];
    const float* ba2       = (const float*)d_in[17];

    static int configured = 0;
    if (!configured) {
        cudaFuncSetAttribute(solution_volume_kernel,
                             cudaFuncAttributeMaxDynamicSharedMemorySize, SMEM_BYTES);
        configured = 1;
    }

    precompute_pt_kernel<<<VVAR, HDIM>>>(gpv, gpr, Wp, bp, Wa1_param, ba1);

    dim3 grid(NPTS / TM, VVAR);
    solution_volume_kernel<<<grid, NTHREADS, SMEM_BYTES>>>(
        coords, enc_g, enc_node,
        Wb1, bb1, Wb2, bb2,
        Wa1_basis, Wa1_node, Wa1_geo,
        Wa2, ba2,
        (float*)d_out);
}

// round 6
// speedup vs baseline: 1.3278x; 1.3278x over previous
#include <cuda_runtime.h>
#include <cstdint>

// Problem constants
#define NPTS   8192
#define VVAR   5
#define HDIM   256
#define TM     32          // points per block tile
#define TMH    16          // points per thread m-half
#define PITCH  36          // smem row pitch (floats): rows 144B (16B-aligned)
#define NTHREADS 256

// smem layout (floats): bufA[256*PITCH] | bufB[256*PITCH] | coord_s[TM*3]
#define BUF_FLOATS   (HDIM * PITCH)
#define COORD_OFF    (2 * BUF_FLOATS)
#define SMEM_FLOATS  (2 * BUF_FLOATS + TM * 3)
#define SMEM_BYTES   (SMEM_FLOATS * 4)

// Precomputed per-(v,feature) constant: pt = ba1 + relu(pe) @ Wa1_param
// 16B-aligned: read via float2 vector loads below.
__device__ __align__(16) float g_pt[VVAR * HDIM];

// ---------- packed f32x2 helpers (Blackwell FFMA2) ----------
__device__ __forceinline__ unsigned long long pack2(float w) {
    unsigned long long r;
    asm("mov.b64 %0, {%1, %1};" : "=l"(r) : "r"(__float_as_uint(w)));
    return r;
}
__device__ __forceinline__ unsigned long long ffma2(unsigned long long a,
                                                    unsigned long long b,
                                                    unsigned long long c) {
    unsigned long long d;
    asm("fma.rn.f32x2 %0, %1, %2, %3;" : "=l"(d) : "l"(a), "l"(b), "l"(c));
    return d;
}
__device__ __forceinline__ float2 unpack2(unsigned long long a) {
    unsigned int lo, hi;
    asm("mov.b64 {%0, %1}, %2;" : "=r"(lo), "=r"(hi) : "l"(a));
    return make_float2(__uint_as_float(lo), __uint_as_float(hi));
}

// TN=2 register-tiled GEMM over the thread's m-half [m0, m0+16):
//   acc0[i] += buf[k][m0+..] * W[k][c0]     (packed pairs of m)
//   acc1[i] += buf[k][m0+..] * W[k][c0+1]
// buf is k-major (rows of PITCH floats). W is float2-view at column pair cg.
// One 16B activation LDS feeds 4 FFMA2.
__device__ __forceinline__ void gemm_acc2(const float* __restrict__ buf,
                                          const float2* __restrict__ W,
                                          unsigned long long* acc0,
                                          unsigned long long* acc1,
                                          int m0) {
    float2 wcur[4], wnxt[4];
#pragma unroll
    for (int j = 0; j < 4; j++) wcur[j] = __ldg(W + j * (HDIM / 2));
#pragma unroll 1
    for (int k4 = 0; k4 < 64; k4++) {
        const float2* Wn = W + (((k4 + 1) & 63) * 4) * (HDIM / 2);  // wraps on last iter
#pragma unroll
        for (int j = 0; j < 4; j++) wnxt[j] = __ldg(Wn + j * (HDIM / 2));
#pragma unroll
        for (int j = 0; j < 4; j++) {
            unsigned long long w0 = pack2(wcur[j].x);
            unsigned long long w1 = pack2(wcur[j].y);
            const float* row = buf + (k4 * 4 + j) * PITCH + m0;
#pragma unroll
            for (int i = 0; i < TMH / 4; i++) {
                ulonglong2 a = *reinterpret_cast<const ulonglong2*>(row + 4 * i);
                acc0[2 * i]     = ffma2(a.x, w0, acc0[2 * i]);
                acc0[2 * i + 1] = ffma2(a.y, w0, acc0[2 * i + 1]);
                acc1[2 * i]     = ffma2(a.x, w1, acc1[2 * i]);
                acc1[2 * i + 1] = ffma2(a.y, w1, acc1[2 * i + 1]);
            }
        }
#pragma unroll
        for (int j = 0; j < 4; j++) wcur[j] = wnxt[j];
    }
}

// ---------- pre-kernel: pt[v][t] = ba1[v][t] + sum_d relu(pe)[d] * Wa1_param[v][d][t] ----------
__global__ void precompute_pt_kernel(const float* __restrict__ gpv,
                                     const float* __restrict__ gpr,
                                     const float* __restrict__ Wp,
                                     const float* __restrict__ bp,
                                     const float* __restrict__ Wa1_param,
                                     const float* __restrict__ ba1) {
    __shared__ float pe_s[HDIM];
    const int t = threadIdx.x;
    const int v = blockIdx.x;
    float r0 = __ldg(gpv + 0) / __ldg(gpr + 0);
    float r1 = __ldg(gpv + 1) / __ldg(gpr + 1);
    float pe = fmaf(r0, __ldg(Wp + t), fmaf(r1, __ldg(Wp + HDIM + t), __ldg(bp + t)));
    pe_s[t] = fmaxf(pe, 0.f);
    __syncthreads();
    float pt = __ldg(ba1 + v * HDIM + t);
    const float* Wpar = Wa1_param + v * HDIM * HDIM + t;
#pragma unroll 8
    for (int d = 0; d < HDIM; d++) pt = fmaf(pe_s[d], __ldg(Wpar + d * HDIM), pt);
    g_pt[v * HDIM + t] = pt;
}

// ---------- main fused kernel ----------
__global__ void __launch_bounds__(NTHREADS, 2)
solution_volume_kernel(const float* __restrict__ coords,      // (N,3)
                       const float* __restrict__ enc_g,       // (N,256)
                       const float* __restrict__ enc_node,    // (N,256)
                       const float* __restrict__ Wb1,         // (V,3,256)
                       const float* __restrict__ bb1,         // (V,256)
                       const float* __restrict__ Wb2,         // (V,256,256)
                       const float* __restrict__ bb2,         // (V,256)
                       const float* __restrict__ Wa1_basis,   // (V,256,256)
                       const float* __restrict__ Wa1_node,    // (V,256,256)
                       const float* __restrict__ Wa1_geo,     // (V,256,256)
                       const float* __restrict__ Wa2,         // (V,256)
                       const float* __restrict__ ba2,         // (V,)
                       float* __restrict__ out)               // (N,V)
{
    extern __shared__ float sm[];
    float* bufA    = sm;
    float* bufB    = sm + BUF_FLOATS;
    float* coord_s = sm + COORD_OFF;

    const int t  = threadIdx.x;
    const int cg = t & 127;              // column-pair owner: features 2cg, 2cg+1
    const int c0 = 2 * cg;               // 0..254
    const int m0 = (t >> 7) * TMH;       // m-half: 0 or 16
    const int v  = blockIdx.y;           // variable
    const int n0 = blockIdx.x * TM;      // first point of tile

    // stage 0: coords tile -> smem
    if (t < TM * 3) coord_s[t] = __ldg(coords + n0 * 3 + t);

    // per-column constants (used in stage 4); c0 <= 254, in bounds
    const float2 ptv = *reinterpret_cast<const float2*>(g_pt + v * HDIM + c0);

    // ---- stage 1: h1 rows 2cg, 2cg+1 over m-half -> bufA (k-major) ----
    {
        const float2* wb = reinterpret_cast<const float2*>(Wb1 + v * 3 * HDIM) + cg;
        float2 w0 = __ldg(wb), w1 = __ldg(wb + HDIM / 2), w2 = __ldg(wb + HDIM);
        float2 b1 = __ldg(reinterpret_cast<const float2*>(bb1 + v * HDIM) + cg);
        __syncthreads();   // coord_s ready
        float* r0p = bufA + c0 * PITCH + m0;
        float* r1p = bufA + (c0 + 1) * PITCH + m0;
#pragma unroll
        for (int mm = 0; mm < TMH; mm++) {
            int m = m0 + mm;
            float cx = coord_s[3 * m + 0], cy = coord_s[3 * m + 1], cz = coord_s[3 * m + 2];
            r0p[mm] = fmaxf(fmaf(w0.x, cx, fmaf(w1.x, cy, fmaf(w2.x, cz, b1.x))), 0.f);
            r1p[mm] = fmaxf(fmaf(w0.y, cx, fmaf(w1.y, cy, fmaf(w2.y, cz, b1.y))), 0.f);
        }
    }
    __syncthreads();

    unsigned long long acc0[TMH / 2], acc1[TMH / 2];
#pragma unroll
    for (int i = 0; i < TMH / 2; i++) { acc0[i] = 0ull; acc1[i] = 0ull; }

    // ---- stage 2: h2 = relu(h1 @ Wb2 + bb2) -> bufB rows 2cg, 2cg+1 ----
    gemm_acc2(bufA, reinterpret_cast<const float2*>(Wb2 + v * HDIM * HDIM) + cg, acc0, acc1, m0);
    {
        float2 b2 = __ldg(reinterpret_cast<const float2*>(bb2 + v * HDIM) + cg);
        float* r0p = bufB + c0 * PITCH + m0;
        float* r1p = bufB + (c0 + 1) * PITCH + m0;
#pragma unroll
        for (int i = 0; i < TMH / 2; i++) {
            float2 f0 = unpack2(acc0[i]);
            float2 f1 = unpack2(acc1[i]);
            r0p[2 * i]     = fmaxf(f0.x + b2.x, 0.f);
            r0p[2 * i + 1] = fmaxf(f0.y + b2.x, 0.f);
            r1p[2 * i]     = fmaxf(f1.x + b2.y, 0.f);
            r1p[2 * i + 1] = fmaxf(f1.y + b2.y, 0.f);
        }
    }
    __syncthreads();   // bufB complete, bufA free

    // ---- stage 3: z accumulation (node + geo + basis) ----
#pragma unroll
    for (int i = 0; i < TMH / 2; i++) { acc0[i] = 0ull; acc1[i] = 0ull; }

    // node tile -> bufA (transposed: bufA[d][m] = enc_node[n0+m][d]); coalesced over t
    {
        float* rowA = bufA + t * PITCH;
#pragma unroll 4
        for (int m = 0; m < TM; m++) rowA[m] = __ldg(enc_node + (size_t)(n0 + m) * HDIM + t);
    }
    __syncthreads();
    gemm_acc2(bufA, reinterpret_cast<const float2*>(Wa1_node + v * HDIM * HDIM) + cg, acc0, acc1, m0);
    __syncthreads();   // all reads of bufA done

    // geo tile -> bufA
    {
        float* rowA = bufA + t * PITCH;
#pragma unroll 4
        for (int m = 0; m < TM; m++) rowA[m] = __ldg(enc_g + (size_t)(n0 + m) * HDIM + t);
    }
    __syncthreads();
    gemm_acc2(bufA, reinterpret_cast<const float2*>(Wa1_geo + v * HDIM * HDIM) + cg, acc0, acc1, m0);
    gemm_acc2(bufB, reinterpret_cast<const float2*>(Wa1_basis + v * HDIM * HDIM) + cg, acc0, acc1, m0);
    __syncthreads();   // all reads of bufA/bufB done before overwrite

    // ---- stage 4: a1 = relu(z + pt); p[c][m] = a1*Wa2 -> bufA rows 2cg, 2cg+1 ----
    {
        float2 w2v = __ldg(reinterpret_cast<const float2*>(Wa2 + v * HDIM) + cg);
        float* r0p = bufA + c0 * PITCH + m0;
        float* r1p = bufA + (c0 + 1) * PITCH + m0;
#pragma unroll
        for (int i = 0; i < TMH / 2; i++) {
            float2 f0 = unpack2(acc0[i]);
            float2 f1 = unpack2(acc1[i]);
            r0p[2 * i]     = fmaxf(f0.x + ptv.x, 0.f) * w2v.x;
            r0p[2 * i + 1] = fmaxf(f0.y + ptv.x, 0.f) * w2v.x;
            r1p[2 * i]     = fmaxf(f1.x + ptv.y, 0.f) * w2v.y;
            r1p[2 * i + 1] = fmaxf(f1.y + ptv.y, 0.f) * w2v.y;
        }
    }
    __syncthreads();

    // ---- stage 5: parallel reduction over 256 feature rows ----
    // warp w sums rows [32w, 32w+32) at column m=lane: conflict-free LDS
    {
        const int lane = t & 31;
        const int w    = t >> 5;
        float s = 0.f;
        const float* base = bufA + (w * 32) * PITCH + lane;
#pragma unroll 8
        for (int kk = 0; kk < 32; kk++) s += base[kk * PITCH];
        bufB[w * 33 + lane] = s;   // bufB free; pitch 33 avoids conflicts
    }
    __syncthreads();
    if (t < TM) {
        float s = __ldg(ba2 + v);
#pragma unroll
        for (int w = 0; w < 8; w++) s += bufB[w * 33 + t];
        out[(size_t)(n0 + t) * VVAR + v] = s;
    }
}

extern "C" void kernel_launch(void* const* d_in, const int* in_sizes, int n_in,
                              void* d_out, int out_size) {
    const float* coords    = (const float*)d_in[0];
    const float* enc_g     = (const float*)d_in[1];
    const float* enc_node  = (const float*)d_in[2];
    const float* gpv       = (const float*)d_in[3];
    const float* gpr       = (const float*)d_in[4];
    const float* Wb1       = (const float*)d_in[5];
    const float* bb1       = (const float*)d_in[6];
    const float* Wb2       = (const float*)d_in[7];
    const float* bb2       = (const float*)d_in[8];
    const float* Wp        = (const float*)d_in[9];
    const float* bp        = (const float*)d_in[10];
    const float* Wa1_basis = (const float*)d_in[11];
    const float* Wa1_node  = (const float*)d_in[12];
    const float* Wa1_geo   = (const float*)d_in[13];
    const float* Wa1_param = (const float*)d_in[14];
    const float* ba1       = (const float*)d_in[15];
    const float* Wa2       = (const float*)d_in[16];
    const float* ba2       = (const float*)d_in[17];

    cudaFuncSetAttribute(solution_volume_kernel,
                         cudaFuncAttributeMaxDynamicSharedMemorySize, SMEM_BYTES);

    precompute_pt_kernel<<<VVAR, HDIM>>>(gpv, gpr, Wp, bp, Wa1_param, ba1);

    dim3 grid(NPTS / TM, VVAR);
    solution_volume_kernel<<<grid, NTHREADS, SMEM_BYTES>>>(
        coords, enc_g, enc_node,
        Wb1, bb1, Wb2, bb2,
        Wa1_basis, Wa1_node, Wa1_geo,
        Wa2, ba2,
        (float*)d_out);
}